// round 1
// baseline (speedup 1.0000x reference)
#include <cuda_runtime.h>
#include <math.h>

#define NN 192
#define TT 20
#define DH 64
#define DE 32
#define DR 32

// Persistent / scratch state (no allocations allowed)
__device__ float g_h[NN*DH], g_c[NN*DH];
__device__ float g_h1[NN*DH], g_c1[NN*DH], g_og[NN*DH];
__device__ float g_h2[NN*DH], g_c2[NN*DH];
__device__ float g_A[NN*DH], g_B[NN*DH], g_a[NN], g_b[NN];
__device__ float g_acc[4];
__device__ float g_v[3];

__global__ void init_kernel(float* out) {
    int tid = blockIdx.x * blockDim.x + threadIdx.x;
    if (tid < NN*DH) { g_h[tid] = 0.f; g_c[tid] = 0.f; }
    if (tid < 4) g_acc[tid] = 0.f;
    if (tid < 3) g_v[tid] = 0.f;
    if (tid < NN*2) out[(TT-1)*NN*2 + tid] = 0.f;  // outputs[T-1] = 0
}

// LSTM cell: one block per node i, 64 threads (one per hidden unit)
__global__ void lstm_kernel(int t, const float* __restrict__ norm,
                            const float* __restrict__ w_in, const float* __restrict__ b_in,
                            const float* __restrict__ w_ih, const float* __restrict__ w_hh,
                            const float* __restrict__ b_ih, const float* __restrict__ b_hh) {
    int i = blockIdx.x;
    int k = threadIdx.x; // 0..63
    __shared__ float sx[DE];
    __shared__ float sh[DH];
    if (k < DE) {
        float n0 = norm[(t*NN + i)*2 + 0];
        float n1 = norm[(t*NN + i)*2 + 1];
        float v = n0 * w_in[k*2 + 0] + n1 * w_in[k*2 + 1] + b_in[k];
        sx[k] = v > 0.f ? v : 0.f;
    }
    sh[k] = g_h[i*DH + k];
    __syncthreads();

    float acc[4];
#pragma unroll
    for (int q = 0; q < 4; q++) {
        int r = q*DH + k;
        float a = b_ih[r] + b_hh[r];
        const float* wi = w_ih + r*DE;
        const float* wh = w_hh + r*DH;
#pragma unroll
        for (int e = 0; e < DE; e++) a += sx[e] * wi[e];
#pragma unroll
        for (int e = 0; e < DH; e++) a += sh[e] * wh[e];
        acc[q] = a;
    }
    float ig = 1.f / (1.f + __expf(-acc[0]));
    float fg = 1.f / (1.f + __expf(-acc[1]));
    float gg = tanhf(acc[2]);
    float og = 1.f / (1.f + __expf(-acc[3]));
    float c1 = fg * g_c[i*DH + k] + ig * gg;
    float h1 = og * tanhf(c1);
    g_c1[i*DH + k] = c1;
    g_h1[i*DH + k] = h1;
    g_og[i*DH + k] = og;
}

// Per-node precompute for gcn: A[i][h], B[i][h], a[i], b[i].
// stage==1 also finalizes the per-step scalar ratios (from gcn0 accumulators).
__global__ void pre_kernel(int stage, const float* __restrict__ w_gate,
                           const float* __restrict__ w_ar) {
    int i = blockIdx.x, h = threadIdx.x;
    if (stage == 1 && i == 0 && h == 0) {
        const float eps = 1e-6f;
        g_v[0] += g_acc[0] / (g_acc[1] * (float)DH + eps);
        g_v[1] += g_acc[2] / (g_acc[3] + eps);
        g_v[2] += g_acc[1] / (float)NN;
        g_acc[0] = g_acc[1] = g_acc[2] = g_acc[3] = 0.f;
    }
    const float* hcur = stage ? g_h2 : g_h1;
    const float* wg = w_gate + stage * DH * 160;
    const float* war = w_ar + stage * 160;

    __shared__ float sh[DH];
    sh[h] = hcur[i*DH + h];
    __syncthreads();

    float A = 0.f, B = 0.f;
    const float* wA = wg + h*160 + 32;
    const float* wB = wg + h*160 + 96;
#pragma unroll
    for (int kk = 0; kk < DH; kk++) { A += sh[kk] * wA[kk]; B += sh[kk] * wB[kk]; }
    g_A[i*DH + h] = A;
    g_B[i*DH + h] = B;
    if (h == 0) { float a = 0.f; for (int kk = 0; kk < DH; kk++) a += sh[kk] * war[32 + kk]; g_a[i] = a; }
    if (h == 1) { float b = 0.f; for (int kk = 0; kk < DH; kk++) b += sh[kk] * war[96 + kk]; g_b[i] = b; }
}

// GCN row kernel: one block per row i, 256 threads.
// stage 0: h1/c1 -> h2/c2, accumulates scalar stats.
// stage 1: h2/c2 -> masked writeback to g_h/g_c + output row.
__global__ void row_kernel(int t, int stage,
                           const float* __restrict__ abs_, const int* __restrict__ seq,
                           const int* __restrict__ nei,
                           const float* __restrict__ w_rel, const float* __restrict__ b_rel,
                           const float* __restrict__ w_gate, const float* __restrict__ b_gate,
                           const float* __restrict__ w_ar, const float* __restrict__ b_ar,
                           const float* __restrict__ w_nei,
                           const float* __restrict__ w_out, const float* __restrict__ b_out,
                           float* __restrict__ out) {
    int i = blockIdx.x;
    int tid = threadIdx.x;
    int lane = tid & 31, warp = tid >> 5;
    int p = stage;
    const float* hcur = stage ? g_h2 : g_h1;
    const float* cin  = stage ? g_c2 : g_c1;
    float* hout = stage ? g_h : g_h2;
    float* cout = stage ? g_c : g_c2;
    const float* wrel = w_rel + p*DR*2;
    const float* brel = b_rel + p*DR;
    const float* wg   = w_gate + p*DH*160;
    const float* bg   = b_gate + p*DH;
    const float* war  = w_ar + p*160;
    const float  bar  = b_ar[p];
    const float* wnei = w_nei + p*DH*DH;

    __shared__ float s_r[NN*33];        // padded r[j][k]
    __shared__ float s_wgT[DR*DH];      // transposed Wg[:, :32]
    __shared__ float s_pos[NN];
    __shared__ int   s_active[NN];
    __shared__ int   s_cnt;
    __shared__ float s_Ai[DH];
    __shared__ float s_msg[8*DH];
    __shared__ float s_msgf[DH];
    __shared__ float s_red[256];
    __shared__ float s_hn[DH];

    for (int idx = tid; idx < DR*DH; idx += 256) {
        int k = idx >> 6, h = idx & 63;
        s_wgT[k*DH + h] = wg[h*160 + k];
    }
    if (tid < DH) s_Ai[tid] = g_A[i*DH + tid];
    if (tid == 0) s_cnt = 0;
    int mi = seq[t*NN + i] > 0;
    float ax = abs_[(t*NN + i)*2 + 0];
    float ay = abs_[(t*NN + i)*2 + 1];
    float a_i = g_a[i];
    __syncthreads();

    float my_neif = 0.f, my_score = -1e30f;
    if (tid < NN) {
        int j = tid;
        int mj = seq[t*NN + j] > 0;
        int nv = nei[(size_t)t*NN*NN + (size_t)i*NN + j];
        float neif = (nv > 0 && mi && mj) ? 1.f : 0.f;
        float cx = ax - abs_[(t*NN + j)*2 + 0];
        float cy = ay - abs_[(t*NN + j)*2 + 1];
        float sc = 0.f;
#pragma unroll
        for (int k = 0; k < DR; k++) {
            float rv = cx * wrel[k*2 + 0] + cy * wrel[k*2 + 1] + brel[k];
            rv = rv > 0.f ? rv : 0.f;
            s_r[j*33 + k] = rv;
            sc += rv * war[k];
        }
        sc += a_i + g_b[j] + bar;
        my_score = (neif > 0.f) ? sc : -1e9f;
        my_neif = neif;
        if (neif > 0.f) { int q = atomicAdd(&s_cnt, 1); s_active[q] = j; }
    }
    __syncthreads();

    // block-wide softmax over j
    s_red[tid] = (tid < NN) ? my_score : -1e30f;
    __syncthreads();
    for (int s = 128; s > 0; s >>= 1) { if (tid < s) s_red[tid] = fmaxf(s_red[tid], s_red[tid + s]); __syncthreads(); }
    float mx = s_red[0];
    __syncthreads();
    float e = (tid < NN) ? __expf(my_score - mx) : 0.f;
    s_red[tid] = e;
    __syncthreads();
    for (int s = 128; s > 0; s >>= 1) { if (tid < s) s_red[tid] += s_red[tid + s]; __syncthreads(); }
    float inv = 1.f / s_red[0];
    __syncthreads();
    float posv = (tid < NN) ? e * inv * my_neif : 0.f;
    if (tid < NN) s_pos[tid] = posv;

    // scalar row-stats (cheap; always computed, only atomically committed for stage 0)
    s_red[tid] = (tid < NN) ? my_neif : 0.f;
    __syncthreads();
    for (int s = 128; s > 0; s >>= 1) { if (tid < s) s_red[tid] += s_red[tid + s]; __syncthreads(); }
    float neiRow = s_red[0];
    __syncthreads();
    s_red[tid] = posv;
    __syncthreads();
    for (int s = 128; s > 0; s >>= 1) { if (tid < s) s_red[tid] = fmaxf(s_red[tid], s_red[tid + s]); __syncthreads(); }
    float maxposRow = s_red[0];
    __syncthreads();

    // Phase 3: gate + message over active neighbors only (8 warps strided)
    float msg0 = 0.f, msg1 = 0.f, v1p = 0.f;
    int cnt = s_cnt;
    for (int a = warp; a < cnt; a += 8) {
        int j = s_active[a];
        float pj = s_pos[j];
        float hj0 = hcur[j*DH + lane];
        float hj1 = hcur[j*DH + 32 + lane];
        float B0 = g_B[j*DH + lane];
        float B1 = g_B[j*DH + 32 + lane];
        float acc0 = s_Ai[lane] + B0 + bg[lane];
        float acc1 = s_Ai[32 + lane] + B1 + bg[32 + lane];
        const float* rj = &s_r[j*33];
#pragma unroll
        for (int k = 0; k < DR; k++) {
            float rv = rj[k];
            acc0 += rv * s_wgT[k*DH + lane];
            acc1 += rv * s_wgT[k*DH + 32 + lane];
        }
        float g0 = 1.f / (1.f + __expf(-acc0));
        float g1 = 1.f / (1.f + __expf(-acc1));
        msg0 += pj * g0 * hj0;
        msg1 += pj * g1 * hj1;
        v1p += g0 + g1;
    }
    s_msg[warp*DH + lane] = msg0;
    s_msg[warp*DH + 32 + lane] = msg1;
    s_red[tid] = v1p;
    __syncthreads();
    for (int s = 128; s > 0; s >>= 1) { if (tid < s) s_red[tid] += s_red[tid + s]; __syncthreads(); }
    float gateSum = s_red[0];
    __syncthreads();

    // Phase 4: reduce msg, update c/h
    if (tid < DH) {
        float m = 0.f;
#pragma unroll
        for (int w = 0; w < 8; w++) m += s_msg[w*DH + tid];
        s_msgf[tid] = m;
    }
    __syncthreads();
    if (tid < DH) {
        float cn = cin[i*DH + tid];
        const float* wn = wnei + tid*DH;
#pragma unroll
        for (int k = 0; k < DH; k++) cn += s_msgf[k] * wn[k];
        float hn = g_og[i*DH + tid] * tanhf(cn);
        if (stage == 1) {
            s_hn[tid] = hn;
            if (mi) { hout[i*DH + tid] = hn; cout[i*DH + tid] = cn; }
        } else {
            hout[i*DH + tid] = hn;
            cout[i*DH + tid] = cn;
        }
    }
    if (stage == 1) {
        __syncthreads();
        if (tid < 2) {
            float o = b_out[tid];
            for (int k = 0; k < DH; k++) o += s_hn[k] * w_out[tid*DH + k];
            out[(t*NN + i)*2 + tid] = mi ? o : 0.f;
        }
    } else {
        if (tid == 0) {
            atomicAdd(&g_acc[0], gateSum);
            atomicAdd(&g_acc[1], neiRow);
            atomicAdd(&g_acc[2], maxposRow);
            atomicAdd(&g_acc[3], neiRow > 0.f ? 1.f : 0.f);
        }
    }
}

__global__ void final_kernel(float* out) {
    int tid = blockIdx.x * blockDim.x + threadIdx.x;
    const int OFF = TT*NN*2;
    if (tid < NN*DH) {
        out[OFF + tid] = g_h[tid];
        out[OFF + NN*DH + tid] = g_c[tid];
    }
    if (tid < 3) out[OFF + 2*NN*DH + tid] = g_v[tid] / (float)TT;
}

extern "C" void kernel_launch(void* const* d_in, const int* in_sizes, int n_in,
                              void* d_out, int out_size) {
    const float* abs_   = (const float*)d_in[0];
    const float* norm   = (const float*)d_in[1];
    // d_in[2] shift_value: unused by reference
    const float* w_in   = (const float*)d_in[3];
    const float* b_in   = (const float*)d_in[4];
    const float* w_ih   = (const float*)d_in[5];
    const float* w_hh   = (const float*)d_in[6];
    const float* b_ih   = (const float*)d_in[7];
    const float* b_hh   = (const float*)d_in[8];
    const float* w_rel  = (const float*)d_in[9];
    const float* b_rel  = (const float*)d_in[10];
    const float* w_gate = (const float*)d_in[11];
    const float* b_gate = (const float*)d_in[12];
    const float* w_ar   = (const float*)d_in[13];
    const float* b_ar   = (const float*)d_in[14];
    const float* w_nei  = (const float*)d_in[15];
    const float* w_out  = (const float*)d_in[16];
    const float* b_out  = (const float*)d_in[17];
    const int*   seq    = (const int*)d_in[18];
    const int*   nei    = (const int*)d_in[19];
    // d_in[20] nei_num: unused by reference
    float* out = (float*)d_out;

    init_kernel<<<48, 256>>>(out);
    for (int t = 0; t < TT - 1; t++) {
        lstm_kernel<<<NN, 64>>>(t, norm, w_in, b_in, w_ih, w_hh, b_ih, b_hh);
        pre_kernel<<<NN, 64>>>(0, w_gate, w_ar);
        row_kernel<<<NN, 256>>>(t, 0, abs_, seq, nei, w_rel, b_rel, w_gate, b_gate,
                                w_ar, b_ar, w_nei, w_out, b_out, out);
        pre_kernel<<<NN, 64>>>(1, w_gate, w_ar);
        row_kernel<<<NN, 256>>>(t, 1, abs_, seq, nei, w_rel, b_rel, w_gate, b_gate,
                                w_ar, b_ar, w_nei, w_out, b_out, out);
    }
    final_kernel<<<48, 256>>>(out);
}